// round 2
// baseline (speedup 1.0000x reference)
#include <cuda_runtime.h>
#include <cuda_bf16.h>
#include <cstdint>

#define N_ANCH   2000000
#define K_SEL    2000
#define OUT_ROWS 1000
#define IMG_SZ   800.0f
#define MIN_SZ   16.0f
#define NMS_TH   0.7f

// control slots
#define CTL_PREFIX 0
#define CTL_RANK   1
#define CTL_NCAND  2
#define CTL_NPAIRS 3

// -------- device scratch (no allocation allowed) --------
__device__ unsigned int       g_keys[N_ANCH];          // 8 MB
__device__ unsigned int       g_hist1[2048];
__device__ unsigned int       g_hist2[2048];
__device__ unsigned int       g_hist3[1024];
__device__ unsigned int       g_ctl[16];
__device__ unsigned long long g_cand[4096];
__device__ float4             g_boxes[K_SEL];
__device__ unsigned char      g_validk[K_SEL];
__device__ unsigned int       g_pairs[2000000];        // 8 MB, >= 2000*1999/2 max pairs

// -------- decode helper (must match reference math) --------
__device__ __forceinline__ float4 decode_box(float4 a, float4 l) {
    float w  = a.z - a.x;
    float h  = a.w - a.y;
    float cx = a.x + 0.5f * w;
    float cy = a.y + 0.5f * h;
    float pcx = cx + l.x * w;
    float pcy = cy + l.y * h;
    float pw  = w * expf(l.z);
    float ph  = h * expf(l.w);
    float x1 = fminf(fmaxf(pcx - 0.5f * pw, 0.0f), IMG_SZ);
    float y1 = fminf(fmaxf(pcy - 0.5f * ph, 0.0f), IMG_SZ);
    float x2 = fminf(fmaxf(pcx + 0.5f * pw, 0.0f), IMG_SZ);
    float y2 = fminf(fmaxf(pcy + 0.5f * ph, 0.0f), IMG_SZ);
    return make_float4(x1, y1, x2, y2);
}

// -------- K0: zero scratch (re-run every graph replay) --------
__global__ void k_zero() {
    for (int i = threadIdx.x; i < 2048; i += blockDim.x) {
        g_hist1[i] = 0u;
        g_hist2[i] = 0u;
        if (i < 1024) g_hist3[i] = 0u;
    }
    if (threadIdx.x < 16)
        g_ctl[threadIdx.x] = (threadIdx.x == CTL_RANK) ? (unsigned)K_SEL : 0u;
}

// -------- K1: decode + key + stage-1 histogram --------
__global__ void k_decode(const float4* __restrict__ locs,
                         const float*  __restrict__ scores,
                         const float4* __restrict__ anchors) {
    __shared__ unsigned int sh[2048];
    for (int t = threadIdx.x; t < 2048; t += blockDim.x) sh[t] = 0u;
    __syncthreads();
    int stride = gridDim.x * blockDim.x;
    for (int i = blockIdx.x * blockDim.x + threadIdx.x; i < N_ANCH; i += stride) {
        float4 b = decode_box(anchors[i], locs[i]);
        bool valid = (b.z - b.x >= MIN_SZ) && (b.w - b.y >= MIN_SZ);
        float s = scores[i];
        unsigned int key = valid ? (__float_as_uint(s) + 1u) : 0u;
        g_keys[i] = key;
        atomicAdd(&sh[key >> 21], 1u);
    }
    __syncthreads();
    for (int t = threadIdx.x; t < 2048; t += blockDim.x)
        if (sh[t]) atomicAdd(&g_hist1[t], sh[t]);
}

// -------- generic radix-select step (1 block) --------
__global__ void k_select(int mode) {
    const unsigned int* hist = (mode == 0) ? g_hist1 : (mode == 1) ? g_hist2 : g_hist3;
    const int nbins = (mode == 2) ? 1024 : 2048;
    __shared__ unsigned int A[2048], B[2048];
    unsigned int K = g_ctl[CTL_RANK];                    // all threads read first
    for (int i = threadIdx.x; i < nbins; i += blockDim.x)
        A[i] = hist[nbins - 1 - i];                      // reversed: i=0 is top bin
    __syncthreads();
    unsigned int* src = A; unsigned int* dst = B;
    for (int d = 1; d < nbins; d <<= 1) {
        for (int i = threadIdx.x; i < nbins; i += blockDim.x)
            dst[i] = src[i] + (i >= d ? src[i - d] : 0u);
        __syncthreads();
        unsigned int* t = src; src = dst; dst = t;
    }
    // src[i] = count of keys in top (i+1) bins
    for (int i = threadIdx.x; i < nbins; i += blockDim.x) {
        unsigned int above = (i == 0) ? 0u : src[i - 1];
        unsigned int cum   = src[i];
        if (above < K && K <= cum) {                     // exactly one winner
            int b = nbins - 1 - i;
            g_ctl[CTL_PREFIX] = g_ctl[CTL_PREFIX] * (unsigned)nbins + (unsigned)b;
            g_ctl[CTL_RANK]   = K - above;
        }
    }
}

// -------- K3: stage-2 histogram over stored keys --------
__global__ void k_hist2() {
    __shared__ unsigned int sh[2048];
    for (int t = threadIdx.x; t < 2048; t += blockDim.x) sh[t] = 0u;
    __syncthreads();
    unsigned int b1 = g_ctl[CTL_PREFIX];
    int stride = gridDim.x * blockDim.x;
    for (int i = blockIdx.x * blockDim.x + threadIdx.x; i < N_ANCH; i += stride) {
        unsigned int key = g_keys[i];
        if ((key >> 21) == b1) atomicAdd(&sh[(key >> 10) & 2047u], 1u);
    }
    __syncthreads();
    for (int t = threadIdx.x; t < 2048; t += blockDim.x)
        if (sh[t]) atomicAdd(&g_hist2[t], sh[t]);
}

// -------- K5: stage-3 histogram --------
__global__ void k_hist3() {
    __shared__ unsigned int sh[1024];
    for (int t = threadIdx.x; t < 1024; t += blockDim.x) sh[t] = 0u;
    __syncthreads();
    unsigned int p2 = g_ctl[CTL_PREFIX];
    int stride = gridDim.x * blockDim.x;
    for (int i = blockIdx.x * blockDim.x + threadIdx.x; i < N_ANCH; i += stride) {
        unsigned int key = g_keys[i];
        if ((key >> 10) == p2) atomicAdd(&sh[key & 1023u], 1u);
    }
    __syncthreads();
    for (int t = threadIdx.x; t < 1024; t += blockDim.x)
        if (sh[t]) atomicAdd(&g_hist3[t], sh[t]);
}

// -------- K7: collect candidates key >= T --------
__global__ void k_collect() {
    unsigned int T = g_ctl[CTL_PREFIX];
    int stride = gridDim.x * blockDim.x;
    for (int i = blockIdx.x * blockDim.x + threadIdx.x; i < N_ANCH; i += stride) {
        unsigned int key = g_keys[i];
        if (key >= T) {
            unsigned int pos = atomicAdd(&g_ctl[CTL_NCAND], 1u);
            if (pos < 4096u)
                g_cand[pos] = ((unsigned long long)key << 32) | (unsigned int)(~(unsigned)i);
        }
    }
}

// -------- K8: sort candidates, build top-2000 boxes --------
__global__ void k_finalize(const float4* __restrict__ locs,
                           const float4* __restrict__ anchors) {
    __shared__ unsigned long long sv[4096];
    int tid = threadIdx.x;
    unsigned int n = g_ctl[CTL_NCAND];
    if (n > 4096u) n = 4096u;
    for (int i = tid; i < 4096; i += blockDim.x)
        sv[i] = (i < (int)n) ? g_cand[i] : 0ULL;
    __syncthreads();
    // bitonic sort, descending
    for (int k = 2; k <= 4096; k <<= 1) {
        for (int j = k >> 1; j > 0; j >>= 1) {
            for (int t = tid; t < 2048; t += blockDim.x) {
                int i = ((t & ~(j - 1)) << 1) | (t & (j - 1));
                int p = i | j;
                unsigned long long va = sv[i], vb = sv[p];
                bool up = ((i & k) == 0);                 // up segment -> descending
                if (up ? (va < vb) : (va > vb)) { sv[i] = vb; sv[p] = va; }
            }
            __syncthreads();
        }
    }
    for (int r = tid; r < K_SEL; r += blockDim.x) {
        unsigned long long v = sv[r];
        unsigned int key = (unsigned int)(v >> 32);
        unsigned int idx = ~(unsigned int)(v & 0xFFFFFFFFu);
        g_validk[r] = (key != 0u) ? 1 : 0;
        float4 box = make_float4(0.f, 0.f, 0.f, 0.f);
        if (key != 0u) box = decode_box(anchors[idx], locs[idx]);
        g_boxes[r] = box;
    }
}

// -------- K9: suppression-edge extraction (iou > th, i < j) --------
__global__ void k_pairs() {
    int bi = blockIdx.y, bj = blockIdx.x;
    if (bi > bj) return;
    __shared__ float4 sb[64];
    int t = threadIdx.x;
    int ig = bi * 64 + t;
    sb[t] = (ig < K_SEL) ? g_boxes[ig] : make_float4(0.f, 0.f, 0.f, 0.f);
    __syncthreads();
    int j = bj * 64 + t;
    if (j >= K_SEL) return;
    float4 bb = g_boxes[j];
    float aj = (bb.z - bb.x) * (bb.w - bb.y);
    #pragma unroll 4
    for (int ii = 0; ii < 64; ii++) {
        int i = bi * 64 + ii;
        if (i >= j || i >= K_SEL) continue;
        float4 ba = sb[ii];
        float xx1 = fmaxf(ba.x, bb.x);
        float yy1 = fmaxf(ba.y, bb.y);
        float xx2 = fminf(ba.z, bb.z);
        float yy2 = fminf(ba.w, bb.w);
        float iw = fmaxf(xx2 - xx1, 0.0f);
        float ih = fmaxf(yy2 - yy1, 0.0f);
        float inter = iw * ih;
        float ai = (ba.z - ba.x) * (ba.w - ba.y);
        float u = fmaxf(ai + aj - inter, 1e-9f);
        if (inter / u > NMS_TH) {
            unsigned int pos = atomicAdd(&g_ctl[CTL_NPAIRS], 1u);
            g_pairs[pos] = ((unsigned)i << 11) | (unsigned)j;
        }
    }
}

// -------- K10: Jacobi greedy-NMS fixed point + compact + write output --------
__global__ void k_resolve(float* __restrict__ outf) {
    __shared__ unsigned char ka[K_SEL], kb[K_SEL];
    __shared__ int changed;
    __shared__ int psA[2048], psB[2048];
    int tid = threadIdx.x;
    int np = (int)g_ctl[CTL_NPAIRS];
    for (int j = tid; j < K_SEL; j += blockDim.x) ka[j] = g_validk[j];
    __syncthreads();
    for (int it = 0; it <= K_SEL; ++it) {
        if (tid == 0) changed = 0;
        for (int j = tid; j < K_SEL; j += blockDim.x) kb[j] = g_validk[j];
        __syncthreads();
        for (int p = tid; p < np; p += blockDim.x) {
            unsigned int pr = g_pairs[p];
            int i = (int)(pr >> 11), j = (int)(pr & 2047u);
            if (ka[i]) kb[j] = 0;
        }
        __syncthreads();
        for (int j = tid; j < K_SEL; j += blockDim.x) {
            if (kb[j] != ka[j]) { changed = 1; ka[j] = kb[j]; }
        }
        __syncthreads();
        int done = (changed == 0);
        __syncthreads();
        if (done) break;
    }
    // stable prefix-sum compaction of kept rows
    for (int i = tid; i < 2048; i += blockDim.x) psA[i] = (i < K_SEL) ? (int)ka[i] : 0;
    __syncthreads();
    int* src = psA; int* dst = psB;
    for (int d = 1; d < 2048; d <<= 1) {
        for (int i = tid; i < 2048; i += blockDim.x)
            dst[i] = src[i] + (i >= d ? src[i - d] : 0);
        __syncthreads();
        int* t2 = src; src = dst; dst = t2;
    }
    float4* out4 = (float4*)outf;
    for (int r = tid; r < OUT_ROWS; r += blockDim.x)
        out4[r] = make_float4(0.f, 0.f, 0.f, 0.f);
    __syncthreads();
    for (int j = tid; j < K_SEL; j += blockDim.x) {
        if (ka[j]) {
            int pos = src[j] - 1;
            if (pos < OUT_ROWS) out4[pos] = g_boxes[j];
        }
    }
}

extern "C" void kernel_launch(void* const* d_in, const int* in_sizes, int n_in,
                              void* d_out, int out_size) {
    const float4* locs    = (const float4*)d_in[0];
    const float*  scores  = (const float*) d_in[1];
    const float4* anchors = (const float4*)d_in[2];
    float* out = (float*)d_out;

    k_zero<<<1, 1024>>>();
    k_decode<<<2048, 256>>>(locs, scores, anchors);
    k_select<<<1, 1024>>>(0);
    k_hist2<<<1024, 256>>>();
    k_select<<<1, 1024>>>(1);
    k_hist3<<<1024, 256>>>();
    k_select<<<1, 1024>>>(2);
    k_collect<<<1024, 256>>>();
    k_finalize<<<1, 1024>>>(locs, anchors);
    k_pairs<<<dim3(32, 32), 64>>>();
    k_resolve<<<1, 1024>>>(out);
}

// round 3
// speedup vs baseline: 1.1199x; 1.1199x over previous
#include <cuda_runtime.h>
#include <cuda_bf16.h>
#include <cstdint>

#define N_ANCH   2000000
#define N_GRP    (N_ANCH / 4)      // 500000 groups of 4
#define K_SEL    2000
#define OUT_ROWS 1000
#define IMG_SZ   800.0f
#define MIN_SZ   16.0f
#define NMS_TH   0.7f

#define CTL_PREFIX 0
#define CTL_RANK   1
#define CTL_NCAND  2
#define CTL_NPAIRS 3

// -------- device scratch --------
__device__ unsigned int       g_keys[N_ANCH];          // 8 MB
__device__ unsigned int       g_hist1[2048];
__device__ unsigned int       g_hist2[2048];
__device__ unsigned int       g_hist3[1024];
__device__ unsigned int       g_ctl[16];
__device__ unsigned long long g_cand[4096];
__device__ float4             g_boxes[K_SEL];
__device__ unsigned char      g_validk[K_SEL];
__device__ unsigned int       g_pairs[2000000];

// -------- decode helper (matches reference math) --------
__device__ __forceinline__ float4 decode_box(float4 a, float4 l) {
    float w  = a.z - a.x;
    float h  = a.w - a.y;
    float cx = a.x + 0.5f * w;
    float cy = a.y + 0.5f * h;
    float pcx = cx + l.x * w;
    float pcy = cy + l.y * h;
    float pw  = w * expf(l.z);
    float ph  = h * expf(l.w);
    float x1 = fminf(fmaxf(pcx - 0.5f * pw, 0.0f), IMG_SZ);
    float y1 = fminf(fmaxf(pcy - 0.5f * ph, 0.0f), IMG_SZ);
    float x2 = fminf(fmaxf(pcx + 0.5f * pw, 0.0f), IMG_SZ);
    float y2 = fminf(fmaxf(pcy + 0.5f * ph, 0.0f), IMG_SZ);
    return make_float4(x1, y1, x2, y2);
}

// warp-aggregated shared histogram add; bin==0xFFFFFFFF -> no-op lane.
// Whole warp must execute this (uniform control flow).
__device__ __forceinline__ void warp_hist_add(unsigned int bin, unsigned int* sh) {
    unsigned int mask = __match_any_sync(0xFFFFFFFFu, bin);
    int lane = (int)(threadIdx.x & 31u);
    int leader = __ffs(mask) - 1;
    if (bin != 0xFFFFFFFFu && lane == leader)
        atomicAdd(&sh[bin], (unsigned int)__popc(mask));
}

// -------- K0: zero scratch --------
__global__ void k_zero() {
    for (int i = threadIdx.x; i < 2048; i += blockDim.x) {
        g_hist1[i] = 0u;
        g_hist2[i] = 0u;
        if (i < 1024) g_hist3[i] = 0u;
    }
    if (threadIdx.x < 16)
        g_ctl[threadIdx.x] = (threadIdx.x == CTL_RANK) ? (unsigned)K_SEL : 0u;
}

// -------- K1: decode + key + stage-1 histogram (vectorized x4) --------
__global__ void __launch_bounds__(256) k_decode(const float4* __restrict__ locs,
                                                const float4* __restrict__ scores4,
                                                const float4* __restrict__ anchors) {
    __shared__ unsigned int sh[2048];
    for (int t = threadIdx.x; t < 2048; t += blockDim.x) sh[t] = 0u;
    __syncthreads();
    int nthreads = gridDim.x * blockDim.x;
    for (int base = blockIdx.x * blockDim.x; base < N_GRP; base += nthreads) {
        int g = base + threadIdx.x;
        bool has = (g < N_GRP);
        unsigned int b0 = 0xFFFFFFFFu, b1 = 0xFFFFFFFFu, b2 = 0xFFFFFFFFu, b3 = 0xFFFFFFFFu;
        if (has) {
            float4 s4 = scores4[g];
            float4 a0 = anchors[4*g+0], a1 = anchors[4*g+1], a2 = anchors[4*g+2], a3 = anchors[4*g+3];
            float4 l0 = locs[4*g+0],    l1 = locs[4*g+1],    l2 = locs[4*g+2],    l3 = locs[4*g+3];
            float4 d0 = decode_box(a0, l0);
            float4 d1 = decode_box(a1, l1);
            float4 d2 = decode_box(a2, l2);
            float4 d3 = decode_box(a3, l3);
            uint4 k4;
            k4.x = ((d0.z-d0.x >= MIN_SZ) && (d0.w-d0.y >= MIN_SZ)) ? (__float_as_uint(s4.x)+1u) : 0u;
            k4.y = ((d1.z-d1.x >= MIN_SZ) && (d1.w-d1.y >= MIN_SZ)) ? (__float_as_uint(s4.y)+1u) : 0u;
            k4.z = ((d2.z-d2.x >= MIN_SZ) && (d2.w-d2.y >= MIN_SZ)) ? (__float_as_uint(s4.z)+1u) : 0u;
            k4.w = ((d3.z-d3.x >= MIN_SZ) && (d3.w-d3.y >= MIN_SZ)) ? (__float_as_uint(s4.w)+1u) : 0u;
            ((uint4*)g_keys)[g] = k4;
            b0 = k4.x >> 21; b1 = k4.y >> 21; b2 = k4.z >> 21; b3 = k4.w >> 21;
        }
        warp_hist_add(b0, sh);
        warp_hist_add(b1, sh);
        warp_hist_add(b2, sh);
        warp_hist_add(b3, sh);
    }
    __syncthreads();
    for (int t = threadIdx.x; t < 2048; t += blockDim.x)
        if (sh[t]) atomicAdd(&g_hist1[t], sh[t]);
}

// -------- generic radix-select step (1 block) --------
__global__ void k_select(int mode) {
    const unsigned int* hist = (mode == 0) ? g_hist1 : (mode == 1) ? g_hist2 : g_hist3;
    const int nbins = (mode == 2) ? 1024 : 2048;
    __shared__ unsigned int A[2048], B[2048];
    unsigned int K = g_ctl[CTL_RANK];
    for (int i = threadIdx.x; i < nbins; i += blockDim.x)
        A[i] = hist[nbins - 1 - i];
    __syncthreads();
    unsigned int* src = A; unsigned int* dst = B;
    for (int d = 1; d < nbins; d <<= 1) {
        for (int i = threadIdx.x; i < nbins; i += blockDim.x)
            dst[i] = src[i] + (i >= d ? src[i - d] : 0u);
        __syncthreads();
        unsigned int* t = src; src = dst; dst = t;
    }
    for (int i = threadIdx.x; i < nbins; i += blockDim.x) {
        unsigned int above = (i == 0) ? 0u : src[i - 1];
        unsigned int cum   = src[i];
        if (above < K && K <= cum) {
            int b = nbins - 1 - i;
            g_ctl[CTL_PREFIX] = g_ctl[CTL_PREFIX] * (unsigned)nbins + (unsigned)b;
            g_ctl[CTL_RANK]   = K - above;
        }
    }
}

// -------- K3: stage-2 histogram (vectorized) --------
__global__ void __launch_bounds__(256) k_hist2() {
    __shared__ unsigned int sh[2048];
    for (int t = threadIdx.x; t < 2048; t += blockDim.x) sh[t] = 0u;
    __syncthreads();
    unsigned int b1 = g_ctl[CTL_PREFIX];
    int stride = gridDim.x * blockDim.x;
    const uint4* keys4 = (const uint4*)g_keys;
    for (int g = blockIdx.x * blockDim.x + threadIdx.x; g < N_GRP; g += stride) {
        uint4 k = keys4[g];
        if ((k.x >> 21) == b1) atomicAdd(&sh[(k.x >> 10) & 2047u], 1u);
        if ((k.y >> 21) == b1) atomicAdd(&sh[(k.y >> 10) & 2047u], 1u);
        if ((k.z >> 21) == b1) atomicAdd(&sh[(k.z >> 10) & 2047u], 1u);
        if ((k.w >> 21) == b1) atomicAdd(&sh[(k.w >> 10) & 2047u], 1u);
    }
    __syncthreads();
    for (int t = threadIdx.x; t < 2048; t += blockDim.x)
        if (sh[t]) atomicAdd(&g_hist2[t], sh[t]);
}

// -------- K5: stage-3 histogram (vectorized) --------
__global__ void __launch_bounds__(256) k_hist3() {
    __shared__ unsigned int sh[1024];
    for (int t = threadIdx.x; t < 1024; t += blockDim.x) sh[t] = 0u;
    __syncthreads();
    unsigned int p2 = g_ctl[CTL_PREFIX];
    int stride = gridDim.x * blockDim.x;
    const uint4* keys4 = (const uint4*)g_keys;
    for (int g = blockIdx.x * blockDim.x + threadIdx.x; g < N_GRP; g += stride) {
        uint4 k = keys4[g];
        if ((k.x >> 10) == p2) atomicAdd(&sh[k.x & 1023u], 1u);
        if ((k.y >> 10) == p2) atomicAdd(&sh[k.y & 1023u], 1u);
        if ((k.z >> 10) == p2) atomicAdd(&sh[k.z & 1023u], 1u);
        if ((k.w >> 10) == p2) atomicAdd(&sh[k.w & 1023u], 1u);
    }
    __syncthreads();
    for (int t = threadIdx.x; t < 1024; t += blockDim.x)
        if (sh[t]) atomicAdd(&g_hist3[t], sh[t]);
}

// -------- K7: collect candidates key >= T (vectorized) --------
__global__ void __launch_bounds__(256) k_collect() {
    unsigned int T = g_ctl[CTL_PREFIX];
    int stride = gridDim.x * blockDim.x;
    const uint4* keys4 = (const uint4*)g_keys;
    for (int g = blockIdx.x * blockDim.x + threadIdx.x; g < N_GRP; g += stride) {
        uint4 k = keys4[g];
        #pragma unroll
        for (int c = 0; c < 4; c++) {
            unsigned int key = (c == 0) ? k.x : (c == 1) ? k.y : (c == 2) ? k.z : k.w;
            if (key >= T) {
                unsigned int i = (unsigned)(4 * g + c);
                unsigned int pos = atomicAdd(&g_ctl[CTL_NCAND], 1u);
                if (pos < 4096u)
                    g_cand[pos] = ((unsigned long long)key << 32) | (unsigned int)(~i);
            }
        }
    }
}

// -------- K8: sort candidates (adaptive 2048/4096), build top-2000 boxes --------
__global__ void k_finalize(const float4* __restrict__ locs,
                           const float4* __restrict__ anchors) {
    __shared__ unsigned long long sv[4096];
    int tid = threadIdx.x;
    unsigned int n = g_ctl[CTL_NCAND];
    if (n > 4096u) n = 4096u;
    int S = (n <= 2048u) ? 2048 : 4096;
    for (int i = tid; i < S; i += blockDim.x)
        sv[i] = (i < (int)n) ? g_cand[i] : 0ULL;
    __syncthreads();
    int half = S >> 1;
    for (int k = 2; k <= S; k <<= 1) {
        for (int j = k >> 1; j > 0; j >>= 1) {
            for (int t = tid; t < half; t += blockDim.x) {
                int i = ((t & ~(j - 1)) << 1) | (t & (j - 1));
                int p = i | j;
                unsigned long long va = sv[i], vb = sv[p];
                bool up = ((i & k) == 0);
                if (up ? (va < vb) : (va > vb)) { sv[i] = vb; sv[p] = va; }
            }
            __syncthreads();
        }
    }
    for (int r = tid; r < K_SEL; r += blockDim.x) {
        unsigned long long v = sv[r];
        unsigned int key = (unsigned int)(v >> 32);
        unsigned int idx = ~(unsigned int)(v & 0xFFFFFFFFu);
        g_validk[r] = (key != 0u) ? 1 : 0;
        float4 box = make_float4(0.f, 0.f, 0.f, 0.f);
        if (key != 0u) box = decode_box(anchors[idx], locs[idx]);
        g_boxes[r] = box;
    }
}

// -------- K9: suppression-edge extraction --------
__global__ void k_pairs() {
    int bi = blockIdx.y, bj = blockIdx.x;
    if (bi > bj) return;
    __shared__ float4 sb[64];
    int t = threadIdx.x;
    int ig = bi * 64 + t;
    sb[t] = (ig < K_SEL) ? g_boxes[ig] : make_float4(0.f, 0.f, 0.f, 0.f);
    __syncthreads();
    int j = bj * 64 + t;
    if (j >= K_SEL) return;
    float4 bb = g_boxes[j];
    float aj = (bb.z - bb.x) * (bb.w - bb.y);
    #pragma unroll 4
    for (int ii = 0; ii < 64; ii++) {
        int i = bi * 64 + ii;
        if (i >= j || i >= K_SEL) continue;
        float4 ba = sb[ii];
        float xx1 = fmaxf(ba.x, bb.x);
        float yy1 = fmaxf(ba.y, bb.y);
        float xx2 = fminf(ba.z, bb.z);
        float yy2 = fminf(ba.w, bb.w);
        float iw = fmaxf(xx2 - xx1, 0.0f);
        float ih = fmaxf(yy2 - yy1, 0.0f);
        float inter = iw * ih;
        float ai = (ba.z - ba.x) * (ba.w - ba.y);
        float u = fmaxf(ai + aj - inter, 1e-9f);
        if (inter / u > NMS_TH) {
            unsigned int pos = atomicAdd(&g_ctl[CTL_NPAIRS], 1u);
            g_pairs[pos] = ((unsigned)i << 11) | (unsigned)j;
        }
    }
}

// -------- K10: Jacobi greedy-NMS fixed point + compact + write output --------
__global__ void k_resolve(float* __restrict__ outf) {
    __shared__ unsigned char ka[K_SEL], kb[K_SEL];
    __shared__ int changed;
    __shared__ int psA[2048], psB[2048];
    int tid = threadIdx.x;
    int np = (int)g_ctl[CTL_NPAIRS];
    for (int j = tid; j < K_SEL; j += blockDim.x) ka[j] = g_validk[j];
    __syncthreads();
    for (int it = 0; it <= K_SEL; ++it) {
        if (tid == 0) changed = 0;
        for (int j = tid; j < K_SEL; j += blockDim.x) kb[j] = g_validk[j];
        __syncthreads();
        for (int p = tid; p < np; p += blockDim.x) {
            unsigned int pr = g_pairs[p];
            int i = (int)(pr >> 11), j = (int)(pr & 2047u);
            if (ka[i]) kb[j] = 0;
        }
        __syncthreads();
        for (int j = tid; j < K_SEL; j += blockDim.x) {
            if (kb[j] != ka[j]) { changed = 1; ka[j] = kb[j]; }
        }
        __syncthreads();
        int done = (changed == 0);
        __syncthreads();
        if (done) break;
    }
    for (int i = tid; i < 2048; i += blockDim.x) psA[i] = (i < K_SEL) ? (int)ka[i] : 0;
    __syncthreads();
    int* src = psA; int* dst = psB;
    for (int d = 1; d < 2048; d <<= 1) {
        for (int i = tid; i < 2048; i += blockDim.x)
            dst[i] = src[i] + (i >= d ? src[i - d] : 0);
        __syncthreads();
        int* t2 = src; src = dst; dst = t2;
    }
    float4* out4 = (float4*)outf;
    for (int r = tid; r < OUT_ROWS; r += blockDim.x)
        out4[r] = make_float4(0.f, 0.f, 0.f, 0.f);
    __syncthreads();
    for (int j = tid; j < K_SEL; j += blockDim.x) {
        if (ka[j]) {
            int pos = src[j] - 1;
            if (pos < OUT_ROWS) out4[pos] = g_boxes[j];
        }
    }
}

extern "C" void kernel_launch(void* const* d_in, const int* in_sizes, int n_in,
                              void* d_out, int out_size) {
    const float4* locs    = (const float4*)d_in[0];
    const float4* scores4 = (const float4*)d_in[1];
    const float4* anchors = (const float4*)d_in[2];
    float* out = (float*)d_out;

    k_zero<<<1, 1024>>>();
    k_decode<<<1954, 256>>>(locs, scores4, anchors);
    k_select<<<1, 1024>>>(0);
    k_hist2<<<1024, 256>>>();
    k_select<<<1, 1024>>>(1);
    k_hist3<<<1024, 256>>>();
    k_select<<<1, 1024>>>(2);
    k_collect<<<1024, 256>>>();
    k_finalize<<<1, 1024>>>(locs, anchors);
    k_pairs<<<dim3(32, 32), 64>>>();
    k_resolve<<<1, 1024>>>(out);
}